// round 1
// baseline (speedup 1.0000x reference)
#include <cuda_runtime.h>
#include <cstddef>

#define D_    2048
#define H_    16
#define S_    2048
#define B_    2
#define KD    128
#define QKV_N 2304   // D + 2*KD

// Scratch (allocation-free rule: __device__ globals)
__device__ float g_qkv[(size_t)B_ * S_ * QKV_N];   // 37.75 MB
__device__ float g_max[(size_t)B_ * H_ * S_];
__device__ float g_sum[(size_t)B_ * H_ * S_];

// ---------------------------------------------------------------------------
// K1: C[M,N] = A[M,K] @ B[K,N] + bias[N]    (lda=K, ldb=N, ldc=N)
// BM=BN=128, BK=16, 256 threads, 8x8 per thread.
// ---------------------------------------------------------------------------
__global__ void __launch_bounds__(256) gemm_bias_nn(
    const float* __restrict__ A, const float* __restrict__ Bm,
    const float* __restrict__ bias, float* __restrict__ C,
    int K, int N)
{
    __shared__ float As[16][132];
    __shared__ float Bs[16][128];

    const int tid = threadIdx.x;
    const int m0 = blockIdx.y * 128;
    const int n0 = blockIdx.x * 128;
    const int tm = (tid / 16) * 8;
    const int tn = (tid % 16) * 8;

    float acc[8][8];
    #pragma unroll
    for (int i = 0; i < 8; i++)
        #pragma unroll
        for (int j = 0; j < 8; j++) acc[i][j] = 0.0f;

    for (int k0 = 0; k0 < K; k0 += 16) {
        #pragma unroll
        for (int l = 0; l < 2; l++) {
            int idx = tid + l * 256;          // 512 float4 for A
            int row = idx >> 2;
            int k4  = (idx & 3) * 4;
            float4 v = *(const float4*)(&A[(size_t)(m0 + row) * K + k0 + k4]);
            As[k4 + 0][row] = v.x;
            As[k4 + 1][row] = v.y;
            As[k4 + 2][row] = v.z;
            As[k4 + 3][row] = v.w;
        }
        #pragma unroll
        for (int l = 0; l < 2; l++) {
            int idx = tid + l * 256;          // 512 float4 for B
            int row = idx >> 5;
            int n4  = (idx & 31) * 4;
            *(float4*)(&Bs[row][n4]) =
                *(const float4*)(&Bm[(size_t)(k0 + row) * N + n0 + n4]);
        }
        __syncthreads();

        #pragma unroll
        for (int kk = 0; kk < 16; kk++) {
            float a[8], b[8];
            #pragma unroll
            for (int i = 0; i < 8; i++) a[i] = As[kk][tm + i];
            #pragma unroll
            for (int j = 0; j < 8; j++) b[j] = Bs[kk][tn + j];
            #pragma unroll
            for (int i = 0; i < 8; i++)
                #pragma unroll
                for (int j = 0; j < 8; j++)
                    acc[i][j] += a[i] * b[j];
        }
        __syncthreads();
    }

    #pragma unroll
    for (int i = 0; i < 8; i++) {
        size_t crow = (size_t)(m0 + tm + i) * N + n0;
        #pragma unroll
        for (int j = 0; j < 8; j++)
            C[crow + tn + j] = acc[i][j] + bias[n0 + tn + j];
    }
}

// ---------------------------------------------------------------------------
// K2: score[bh, s, t] = (q[b,s,h,:] . k[b,t,:]) / 16384
// A = qkv + b*S*QKV_N + h*KD   (ld QKV_N), B = qkv + b*S*QKV_N + D (ld QKV_N)
// BM=BN=128, BK=32 (K total = 128), 256 threads, 8x8 per thread.
// ---------------------------------------------------------------------------
__global__ void __launch_bounds__(256) score_kernel(float* __restrict__ score)
{
    __shared__ float As[32][132];
    __shared__ float Bs[32][132];

    const int bh = blockIdx.z;
    const int b  = bh >> 4;
    const int h  = bh & 15;
    const float* A  = g_qkv + (size_t)b * S_ * QKV_N + h * KD;
    const float* Bk = g_qkv + (size_t)b * S_ * QKV_N + D_;
    float* C = score + (size_t)bh * S_ * S_;

    const int m0 = blockIdx.y * 128;
    const int n0 = blockIdx.x * 128;
    const int tid = threadIdx.x;
    const int tm = (tid / 16) * 8;
    const int tn = (tid % 16) * 8;

    float acc[8][8];
    #pragma unroll
    for (int i = 0; i < 8; i++)
        #pragma unroll
        for (int j = 0; j < 8; j++) acc[i][j] = 0.0f;

    for (int k0 = 0; k0 < KD; k0 += 32) {
        #pragma unroll
        for (int l = 0; l < 4; l++) {
            int idx = tid + l * 256;       // 1024 float4 each for A and B
            int row = idx >> 3;
            int k4  = (idx & 7) * 4;
            float4 v = *(const float4*)(&A[(size_t)(m0 + row) * QKV_N + k0 + k4]);
            As[k4 + 0][row] = v.x;
            As[k4 + 1][row] = v.y;
            As[k4 + 2][row] = v.z;
            As[k4 + 3][row] = v.w;
            float4 w = *(const float4*)(&Bk[(size_t)(n0 + row) * QKV_N + k0 + k4]);
            Bs[k4 + 0][row] = w.x;
            Bs[k4 + 1][row] = w.y;
            Bs[k4 + 2][row] = w.z;
            Bs[k4 + 3][row] = w.w;
        }
        __syncthreads();

        #pragma unroll
        for (int kk = 0; kk < 32; kk++) {
            float a[8], bb[8];
            #pragma unroll
            for (int i = 0; i < 8; i++) a[i] = As[kk][tm + i];
            #pragma unroll
            for (int j = 0; j < 8; j++) bb[j] = Bs[kk][tn + j];
            #pragma unroll
            for (int i = 0; i < 8; i++)
                #pragma unroll
                for (int j = 0; j < 8; j++)
                    acc[i][j] += a[i] * bb[j];
        }
        __syncthreads();
    }

    const float inv = 1.0f / 16384.0f;
    #pragma unroll
    for (int i = 0; i < 8; i++) {
        size_t crow = (size_t)(m0 + tm + i) * S_ + n0;
        #pragma unroll
        for (int j = 0; j < 8; j++)
            C[crow + tn + j] = acc[i][j] * inv;
    }
}

// ---------------------------------------------------------------------------
// K3: per-row max and sum of exp over the score rows (65536 rows x 2048)
// ---------------------------------------------------------------------------
__global__ void __launch_bounds__(256) softmax_stats(const float* __restrict__ score)
{
    const int row = blockIdx.x;
    const float* p = score + (size_t)row * S_;
    const int tid  = threadIdx.x;
    const int lane = tid & 31;
    const int wid  = tid >> 5;

    __shared__ float red[8];

    float vals[8];
    float vmax = -1e30f;
    #pragma unroll
    for (int i = 0; i < 8; i++) {
        vals[i] = p[tid + i * 256];
        vmax = fmaxf(vmax, vals[i]);
    }
    #pragma unroll
    for (int o = 16; o > 0; o >>= 1)
        vmax = fmaxf(vmax, __shfl_xor_sync(0xFFFFFFFFu, vmax, o));
    if (lane == 0) red[wid] = vmax;
    __syncthreads();
    float m = red[0];
    #pragma unroll
    for (int w = 1; w < 8; w++) m = fmaxf(m, red[w]);
    __syncthreads();

    float s = 0.0f;
    #pragma unroll
    for (int i = 0; i < 8; i++) s += __expf(vals[i] - m);
    #pragma unroll
    for (int o = 16; o > 0; o >>= 1)
        s += __shfl_xor_sync(0xFFFFFFFFu, s, o);
    if (lane == 0) red[wid] = s;
    __syncthreads();
    if (tid == 0) {
        float t = 0.0f;
        #pragma unroll
        for (int w = 0; w < 8; w++) t += red[w];
        g_max[row] = m;
        g_sum[row] = t;
    }
}

// ---------------------------------------------------------------------------
// K4: atten[bh,s,:] = (exp(score[bh,s,:]-m)/l) @ v   and res transpose write.
// BM=128, BN=128(=KD), BK=32, K loop over S_=2048. exp fused into A-tile load.
// ---------------------------------------------------------------------------
__global__ void __launch_bounds__(256) attn_pv(
    const float* __restrict__ score, float* __restrict__ atten,
    float* __restrict__ res)
{
    __shared__ float As[32][132];
    __shared__ float Bs[32][128];
    __shared__ float smax[128];
    __shared__ float sinv[128];

    const int bh = blockIdx.y;
    const int b  = bh >> 4;
    const int h  = bh & 15;
    const float* A = score + (size_t)bh * S_ * S_;
    const float* V = g_qkv + (size_t)b * S_ * QKV_N + D_ + KD;  // ld QKV_N
    const int m0  = blockIdx.x * 128;
    const int tid = threadIdx.x;

    if (tid < 128) {
        int r = bh * S_ + m0 + tid;
        smax[tid] = g_max[r];
        sinv[tid] = 1.0f / g_sum[r];
    }
    __syncthreads();

    const int tm = (tid / 16) * 8;
    const int tn = (tid % 16) * 8;

    float acc[8][8];
    #pragma unroll
    for (int i = 0; i < 8; i++)
        #pragma unroll
        for (int j = 0; j < 8; j++) acc[i][j] = 0.0f;

    for (int k0 = 0; k0 < S_; k0 += 32) {
        #pragma unroll
        for (int l = 0; l < 4; l++) {
            int idx = tid + l * 256;
            // A tile (128 rows x 32 k), exp applied on the fly
            int row = idx >> 3;
            int k4  = (idx & 7) * 4;
            float4 v = *(const float4*)(&A[(size_t)(m0 + row) * S_ + k0 + k4]);
            float mx = smax[row];
            As[k4 + 0][row] = __expf(v.x - mx);
            As[k4 + 1][row] = __expf(v.y - mx);
            As[k4 + 2][row] = __expf(v.z - mx);
            As[k4 + 3][row] = __expf(v.w - mx);
            // B tile (32 k-rows x 128 n)
            int vrow = idx >> 5;
            int n4   = (idx & 31) * 4;
            *(float4*)(&Bs[vrow][n4]) =
                *(const float4*)(&V[(size_t)(k0 + vrow) * QKV_N + n4]);
        }
        __syncthreads();

        #pragma unroll
        for (int kk = 0; kk < 32; kk++) {
            float a[8], bb[8];
            #pragma unroll
            for (int i = 0; i < 8; i++) a[i] = As[kk][tm + i];
            #pragma unroll
            for (int j = 0; j < 8; j++) bb[j] = Bs[kk][tn + j];
            #pragma unroll
            for (int i = 0; i < 8; i++)
                #pragma unroll
                for (int j = 0; j < 8; j++)
                    acc[i][j] += a[i] * bb[j];
        }
        __syncthreads();
    }

    #pragma unroll
    for (int i = 0; i < 8; i++) {
        int s = m0 + tm + i;
        float il = sinv[tm + i];
        size_t arow = (size_t)bh * S_ * KD + (size_t)s * KD + tn;
        size_t rrow = ((size_t)(b * S_ + s)) * D_ + h * KD + tn;
        #pragma unroll
        for (int j = 0; j < 8; j++) {
            float o = acc[i][j] * il;
            atten[arow + j] = o;
            res[rrow + j]   = o;
        }
    }
}

// ---------------------------------------------------------------------------
extern "C" void kernel_launch(void* const* d_in, const int* in_sizes, int n_in,
                              void* d_out, int out_size)
{
    const float* in_x  = (const float*)d_in[0];
    const float* W_sc  = (const float*)d_in[1];
    const float* b_sc  = (const float*)d_in[2];
    const float* W_qkv = (const float*)d_in[3];
    const float* b_qkv = (const float*)d_in[4];

    float* out       = (float*)d_out;
    float* score     = out;                                      // B*H*S*S
    float* atten     = score + (size_t)B_ * H_ * S_ * S_;        // B*H*S*KD
    float* res       = atten + (size_t)B_ * H_ * S_ * KD;        // B*S*D
    float* short_cut = res   + (size_t)B_ * S_ * D_;             // B*S*D

    float* qkv_s = nullptr;
    cudaGetSymbolAddress((void**)&qkv_s, g_qkv);

    // short_cut = X @ W_sc + b_sc
    gemm_bias_nn<<<dim3(D_ / 128, (B_ * S_) / 128), 256>>>(
        in_x, W_sc, b_sc, short_cut, D_, D_);
    // qkv = X @ W_qkv + b_qkv
    gemm_bias_nn<<<dim3(QKV_N / 128, (B_ * S_) / 128), 256>>>(
        in_x, W_qkv, b_qkv, qkv_s, D_, QKV_N);
    // score = q k^T / kd^2
    score_kernel<<<dim3(S_ / 128, S_ / 128, B_ * H_), 256>>>(score);
    // softmax stats
    softmax_stats<<<B_ * H_ * S_, 256>>>(score);
    // atten + res
    attn_pv<<<dim3(S_ / 128, B_ * H_), 256>>>(score, atten, res);
}